// round 1
// baseline (speedup 1.0000x reference)
#include <cuda_runtime.h>
#include <math.h>

#define BATCH 4
#define T 2048
#define H 1024
#define NHEAD 16
#define HD 64
#define FF 4096
#define BT (BATCH * T)   // 8192 rows

// ---------------- scratch (allocation-free: __device__ globals) --------------
__device__ float g_q[BT * H];
__device__ float g_k[BT * H];
__device__ float g_v[BT * H];
__device__ float g_x1[BT * H];     // x + attn_out
__device__ float g_h[BT * FF];     // gelu(x1 @ W1 + b1)

// ---------------- helpers ----------------------------------------------------
__device__ __forceinline__ float gelu_tanh(float x) {
    // jax.nn.gelu default (approximate=True)
    const float c = 0.7978845608028654f;     // sqrt(2/pi)
    float t = tanhf(c * (x + 0.044715f * x * x * x));
    return 0.5f * x * (1.0f + t);
}

// ---------------- generic SGEMM: C = A[MxK] @ B[KxN] + bias (+act)(+res) -----
// BM=BN=128, BK=8, 256 threads, 8x8 micro-tile per thread.
__global__ __launch_bounds__(256, 2)
void sgemm_kernel(const float* __restrict__ A, const float* __restrict__ B,
                  const float* __restrict__ bias, const float* __restrict__ res,
                  float* __restrict__ C, int M, int N, int K, int act)
{
    __shared__ float As[8][128];
    __shared__ float Bs[8][128];

    const int bx = blockIdx.x;   // N tile
    const int by = blockIdx.y;   // M tile
    const int tid = threadIdx.x;

    // A-load mapping: 128 rows x 8 cols, float4 per thread (2 per row)
    const int arow = tid >> 1;
    const int acol = (tid & 1) * 4;
    // B-load mapping: 8 rows x 128 cols, float4 per thread
    const int brow = tid >> 5;
    const int bcol = (tid & 31) * 4;
    // compute mapping
    const int tx = tid & 15;
    const int ty = tid >> 4;

    const float* Aptr = A + (size_t)(by * 128 + arow) * K + acol;
    const float* Bptr = B + (size_t)brow * N + bx * 128 + bcol;

    float acc[8][8];
    #pragma unroll
    for (int i = 0; i < 8; i++)
        #pragma unroll
        for (int j = 0; j < 8; j++) acc[i][j] = 0.0f;

    for (int k0 = 0; k0 < K; k0 += 8) {
        float4 av = *(const float4*)(Aptr + k0);
        As[acol + 0][arow] = av.x;
        As[acol + 1][arow] = av.y;
        As[acol + 2][arow] = av.z;
        As[acol + 3][arow] = av.w;
        *(float4*)&Bs[brow][bcol] = *(const float4*)(Bptr + (size_t)k0 * N);
        __syncthreads();

        #pragma unroll
        for (int k = 0; k < 8; k++) {
            float a[8], b[8];
            *(float4*)(a)     = *(const float4*)&As[k][ty * 8];
            *(float4*)(a + 4) = *(const float4*)&As[k][ty * 8 + 4];
            *(float4*)(b)     = *(const float4*)&Bs[k][tx * 8];
            *(float4*)(b + 4) = *(const float4*)&Bs[k][tx * 8 + 4];
            #pragma unroll
            for (int i = 0; i < 8; i++)
                #pragma unroll
                for (int j = 0; j < 8; j++)
                    acc[i][j] += a[i] * b[j];
        }
        __syncthreads();
    }

    // epilogue
    #pragma unroll
    for (int i = 0; i < 8; i++) {
        const int row = by * 128 + ty * 8 + i;
        const int colb = bx * 128 + tx * 8;
        float* crow = C + (size_t)row * N + colb;
        const float* rrow = res ? (res + (size_t)row * N + colb) : nullptr;
        #pragma unroll
        for (int j = 0; j < 8; j++) {
            float v = acc[i][j] + bias[colb + j];
            if (act) v = gelu_tanh(v);
            if (rrow) v += rrow[j];
            crow[j] = v;
        }
    }
}

// ---------------- flash attention + residual ---------------------------------
// grid: (qt = T/64, b*NHEAD). block: 256 threads (8 warps, 8 query rows each).
// smem: Qs[64*64] | Ks[64*65] | Vs[64*64] | Ps[8*8*64]
#define ATT_SMEM_FLOATS (64*64 + 64*65 + 64*64 + 8*8*64)

__global__ __launch_bounds__(256)
void attn_kernel(const float* __restrict__ x, float* __restrict__ x1)
{
    extern __shared__ float sm[];
    float* Qs = sm;                         // 4096
    float* Ks = sm + 4096;                  // 4160 (stride 65)
    float* Vs = sm + 4096 + 4160;           // 4096
    float* Ps = sm + 4096 + 4160 + 4096;    // 4096

    const int qt   = blockIdx.x;
    const int bh   = blockIdx.y;
    const int b    = bh >> 4;
    const int h    = bh & 15;
    const int tid  = threadIdx.x;
    const int lane = tid & 31;
    const int w    = tid >> 5;

    const size_t headoff = (size_t)b * T * H + (size_t)h * HD;
    const float* Qg = g_q + headoff;
    const float* Kg = g_k + headoff;
    const float* Vg = g_v + headoff;

    // load Q tile, pre-scaled by 1/sqrt(H) = 1/32
    #pragma unroll
    for (int i = 0; i < 4; i++) {
        int e = tid + 256 * i;             // 0..1023
        int r = e >> 4;
        int c = (e & 15) << 2;
        float4 v = *(const float4*)(Qg + (size_t)(qt * 64 + r) * H + c);
        Qs[r * 64 + c + 0] = v.x * 0.03125f;
        Qs[r * 64 + c + 1] = v.y * 0.03125f;
        Qs[r * 64 + c + 2] = v.z * 0.03125f;
        Qs[r * 64 + c + 3] = v.w * 0.03125f;
    }

    float m[8], l[8];
    float2 o[8];
    #pragma unroll
    for (int r = 0; r < 8; r++) { m[r] = -1e30f; l[r] = 0.0f; o[r] = make_float2(0.f, 0.f); }

    __syncthreads();

    for (int kt = 0; kt <= qt; kt++) {
        // load K (padded rows, scalar stores) and V (float4) tiles
        #pragma unroll
        for (int i = 0; i < 4; i++) {
            int e = tid + 256 * i;
            int r = e >> 4;
            int c = (e & 15) << 2;
            float4 kv = *(const float4*)(Kg + (size_t)(kt * 64 + r) * H + c);
            Ks[r * 65 + c + 0] = kv.x;
            Ks[r * 65 + c + 1] = kv.y;
            Ks[r * 65 + c + 2] = kv.z;
            Ks[r * 65 + c + 3] = kv.w;
            float4 vv = *(const float4*)(Vg + (size_t)(kt * 64 + r) * H + c);
            *(float4*)&Vs[r * 64 + c] = vv;
        }
        __syncthreads();

        // S = Q @ K^T : each lane handles keys (lane, lane+32) for 8 rows
        float s0[8], s1[8];
        const float* k0p = &Ks[lane * 65];
        const float* k1p = &Ks[(lane + 32) * 65];
        #pragma unroll
        for (int rg = 0; rg < 2; rg++) {
            const float* qb = &Qs[(w * 8 + rg * 4) * 64];
            float a0[4], a1[4];
            #pragma unroll
            for (int rr = 0; rr < 4; rr++) { a0[rr] = 0.f; a1[rr] = 0.f; }
            #pragma unroll 16
            for (int d = 0; d < 64; d++) {
                float k0 = k0p[d];
                float k1 = k1p[d];
                #pragma unroll
                for (int rr = 0; rr < 4; rr++) {
                    float qv = qb[rr * 64 + d];
                    a0[rr] += qv * k0;
                    a1[rr] += qv * k1;
                }
            }
            #pragma unroll
            for (int rr = 0; rr < 4; rr++) { s0[rg * 4 + rr] = a0[rr]; s1[rg * 4 + rr] = a1[rr]; }
        }

        // online softmax per row
        const bool diag = (kt == qt);
        #pragma unroll
        for (int r = 0; r < 8; r++) {
            const int rowi = w * 8 + r;
            float v0 = s0[r], v1 = s1[r];
            const bool m0 = (!diag) || (lane <= rowi);
            const bool m1 = (!diag) || (lane + 32 <= rowi);
            if (!m0) v0 = -1e30f;
            if (!m1) v1 = -1e30f;
            float mx = fmaxf(v0, v1);
            #pragma unroll
            for (int off = 16; off; off >>= 1)
                mx = fmaxf(mx, __shfl_xor_sync(0xffffffffu, mx, off));
            const float mn = fmaxf(m[r], mx);
            const float alpha = __expf(m[r] - mn);
            const float p0 = m0 ? __expf(v0 - mn) : 0.0f;
            const float p1 = m1 ? __expf(v1 - mn) : 0.0f;
            float ps = p0 + p1;
            #pragma unroll
            for (int off = 16; off; off >>= 1)
                ps += __shfl_xor_sync(0xffffffffu, ps, off);
            l[r] = l[r] * alpha + ps;
            m[r] = mn;
            o[r].x *= alpha;
            o[r].y *= alpha;
            Ps[w * 512 + r * 64 + lane]      = p0;
            Ps[w * 512 + r * 64 + lane + 32] = p1;
        }
        __syncwarp();

        // O += P @ V  (lane owns dims 2*lane, 2*lane+1)
        const float* pw = &Ps[w * 512];
        #pragma unroll 8
        for (int j = 0; j < 64; j++) {
            float2 v = *(const float2*)&Vs[j * 64 + lane * 2];
            #pragma unroll
            for (int r = 0; r < 8; r++) {
                float p = pw[r * 64 + j];
                o[r].x += p * v.x;
                o[r].y += p * v.y;
            }
        }
        __syncthreads();
    }

    // epilogue: x1 = x + softmax(QK^T)V
    #pragma unroll
    for (int r = 0; r < 8; r++) {
        const int trow = qt * 64 + w * 8 + r;
        const size_t base = (size_t)b * T * H + (size_t)trow * H + (size_t)h * HD + lane * 2;
        const float inv = 1.0f / l[r];
        x1[base + 0] = x[base + 0] + o[r].x * inv;
        x1[base + 1] = x[base + 1] + o[r].y * inv;
    }
}

// ---------------- launch -----------------------------------------------------
extern "C" void kernel_launch(void* const* d_in, const int* in_sizes, int n_in,
                              void* d_out, int out_size)
{
    const float* x  = (const float*)d_in[0];
    const float* Wq = (const float*)d_in[1];
    const float* bq = (const float*)d_in[2];
    const float* Wk = (const float*)d_in[3];
    const float* bk = (const float*)d_in[4];
    const float* Wv = (const float*)d_in[5];
    const float* bv = (const float*)d_in[6];
    const float* W1 = (const float*)d_in[7];
    const float* b1 = (const float*)d_in[8];
    const float* W2 = (const float*)d_in[9];
    const float* b2 = (const float*)d_in[10];
    float* out = (float*)d_out;

    float *q, *k, *v, *x1, *hbuf;
    cudaGetSymbolAddress((void**)&q,    g_q);
    cudaGetSymbolAddress((void**)&k,    g_k);
    cudaGetSymbolAddress((void**)&v,    g_v);
    cudaGetSymbolAddress((void**)&x1,   g_x1);
    cudaGetSymbolAddress((void**)&hbuf, g_h);

    const dim3 blk(256);
    const dim3 gQKV(H / 128, BT / 128);      // (8, 64)
    const dim3 gFF(FF / 128, BT / 128);      // (32, 64)

    sgemm_kernel<<<gQKV, blk>>>(x, Wq, bq, nullptr, q, BT, H, H, 0);
    sgemm_kernel<<<gQKV, blk>>>(x, Wk, bk, nullptr, k, BT, H, H, 0);
    sgemm_kernel<<<gQKV, blk>>>(x, Wv, bv, nullptr, v, BT, H, H, 0);

    const int att_smem = ATT_SMEM_FLOATS * (int)sizeof(float);   // 65792
    cudaFuncSetAttribute(attn_kernel, cudaFuncAttributeMaxDynamicSharedMemorySize, att_smem);
    attn_kernel<<<dim3(T / 64, BATCH * NHEAD), blk, att_smem>>>(x, x1);

    sgemm_kernel<<<gFF,  blk>>>(x1,   W1, b1, nullptr, hbuf, BT, FF, H, 1);
    sgemm_kernel<<<gQKV, blk>>>(hbuf, W2, b2, x1,      out,  BT, H, FF, 0);
}

// round 3
// speedup vs baseline: 2.2332x; 2.2332x over previous
#include <cuda_runtime.h>
#include <math.h>
#include <stdint.h>

#define BATCH 4
#define T 2048
#define H 1024
#define NHEAD 16
#define HD 64
#define FF 4096
#define BT (BATCH * T)   // 8192 rows

// ---------------- scratch (allocation-free: __device__ globals) --------------
__device__ float g_q[BT * H];
__device__ float g_k[BT * H];
__device__ float g_v[BT * H];
__device__ float g_x1[BT * H];     // x + attn_out (exact)
__device__ float g_x1r[BT * H];    // tf32-rounded, k-permuted x1
__device__ float g_xr[BT * H];     // tf32-rounded, k-permuted x
__device__ float g_h[BT * FF];     // tf32-rounded, k-permuted gelu(x1@W1+b1)
__device__ float g_wqt[H * H];     // transposed + rounded + k-permuted weights [N,K]
__device__ float g_wkt[H * H];
__device__ float g_wvt[H * H];
__device__ float g_w1t[H * FF];    // [FF, H]
__device__ float g_w2t[FF * H];    // [H, FF]

// ---------------- helpers ----------------------------------------------------
__device__ __forceinline__ uint32_t smem_u32(const void* p) {
    uint32_t a;
    asm("{ .reg .u64 t; cvta.to.shared.u64 t, %1; cvt.u32.u64 %0, t; }"
        : "=r"(a) : "l"(p));
    return a;
}
__device__ __forceinline__ float rna_tf32(float x) {
    uint32_t u;
    asm("cvt.rna.tf32.f32 %0, %1;" : "=r"(u) : "f"(x));
    return __uint_as_float(u);
}
__device__ __forceinline__ float ftanh(float x) {
    float y;
    asm("tanh.approx.f32 %0, %1;" : "=f"(y) : "f"(x));
    return y;
}
__device__ __forceinline__ float gelu_f(float x) {
    return 0.5f * x * (1.0f + ftanh(0.7978845608028654f * (x + 0.044715f * x * x * x)));
}
// physical position of logical k-index l within its 8-group: [k0,k4,k1,k5,k2,k6,k3,k7]
__device__ __forceinline__ int perm8(int l) {
    return (l < 4) ? (2 * l) : (2 * (l - 4) + 1);
}
__device__ __forceinline__ uint2 lds64(uint32_t addr) {
    uint2 v;
    asm volatile("ld.shared.v2.b32 {%0, %1}, [%2];" : "=r"(v.x), "=r"(v.y) : "r"(addr));
    return v;
}
__device__ __forceinline__ void mma8(float* d, uint32_t a0, uint32_t a1, uint32_t a2,
                                     uint32_t a3, uint32_t b0, uint32_t b1) {
    asm volatile(
        "mma.sync.aligned.m16n8k8.row.col.f32.tf32.tf32.f32 "
        "{%0,%1,%2,%3}, {%4,%5,%6,%7}, {%8,%9}, {%0,%1,%2,%3};"
        : "+f"(d[0]), "+f"(d[1]), "+f"(d[2]), "+f"(d[3])
        : "r"(a0), "r"(a1), "r"(a2), "r"(a3), "r"(b0), "r"(b1));
}

// ---------------- prep kernels ------------------------------------------------
// round to tf32 + permute k within 8-groups (contiguous layout transform)
__global__ void round_perm_k(const float* __restrict__ in, float* __restrict__ out, int n) {
    int i = (blockIdx.x * blockDim.x + threadIdx.x) * 8;
    if (i < n) {
        float4 lo = *(const float4*)(in + i);
        float4 hi = *(const float4*)(in + i + 4);
        float4 o0, o1;
        o0.x = rna_tf32(lo.x); o0.y = rna_tf32(hi.x);
        o0.z = rna_tf32(lo.y); o0.w = rna_tf32(hi.y);
        o1.x = rna_tf32(lo.z); o1.y = rna_tf32(hi.z);
        o1.z = rna_tf32(lo.w); o1.w = rna_tf32(hi.w);
        *(float4*)(out + i)     = o0;
        *(float4*)(out + i + 4) = o1;
    }
}

// Wt[n, kperm] = rna(W[k, n]);  W is [K,N] row-major
__global__ void transpose_rna_perm_k(const float* __restrict__ W, float* __restrict__ Wt,
                                     int K, int N) {
    __shared__ float t[32][33];
    int n0 = blockIdx.x * 32, k0 = blockIdx.y * 32;
    int tx = threadIdx.x, ty = threadIdx.y;
    #pragma unroll
    for (int j = ty; j < 32; j += 8)
        t[j][tx] = W[(size_t)(k0 + j) * N + n0 + tx];
    __syncthreads();
    int kk = k0 + tx;
    int kphys = (kk & ~7) + perm8(kk & 7);
    #pragma unroll
    for (int j = ty; j < 32; j += 8)
        Wt[(size_t)(n0 + j) * K + kphys] = rna_tf32(t[tx][j]);
}

// ---------------- tf32 mma.sync GEMM ------------------------------------------
// C[M, N] = A[M,Kperm] @ Bt[N,Kperm]^T. Tile 128x128 per CTA, BK=32, 3 stages.
// mode 0: C = acc + bias              (QKV; z selects weight/bias/out)
// mode 1: C = rna(gelu(acc+bias)), column-permuted   (MLP1 -> g_h)
// mode 2: C = acc + bias + res        (MLP2 -> out)
#define STAGE_BYTES 32768          // 16KB A + 16KB B
#define GEMM_SMEM   (3 * STAGE_BYTES)

__global__ __launch_bounds__(256, 2)
void gemm_tf32(const float* __restrict__ A,
               const float* __restrict__ B0t, const float* __restrict__ B1t,
               const float* __restrict__ B2t,
               const float* __restrict__ bias0, const float* __restrict__ bias1,
               const float* __restrict__ bias2,
               float* __restrict__ C0, float* __restrict__ C1, float* __restrict__ C2,
               const float* __restrict__ res,
               int K, int N, int mode)
{
    extern __shared__ float sf[];
    const uint32_t sbase = smem_u32(sf);

    const float* Bt = B0t; const float* bias = bias0; float* C = C0;
    if (blockIdx.z == 1) { Bt = B1t; bias = bias1; C = C1; }
    else if (blockIdx.z == 2) { Bt = B2t; bias = bias2; C = C2; }

    const int tid  = threadIdx.x;
    const int lane = tid & 31;
    const int w    = tid >> 5;
    const int g    = lane >> 2;       // 0..7
    const int c    = lane & 3;        // 0..3
    const int wm   = w & 3;           // M quadrant (32 rows)
    const int wn   = w >> 1 & 2 ? 0 : 0; // placeholder (computed below)
    const int wnn  = w >> 2;          // N half (64 cols)
    const int bx = blockIdx.x, by = blockIdx.y;
    const int nk = K >> 5;

    // ---- loader mapping: 256 threads x 8 chunks of 16B per stage ----
    const int rowl = tid >> 3;        // 0..31
    const int cj   = tid & 7;         // 16B chunk in 128B row
    const uint32_t soA = (uint32_t)(rowl * 128 + ((cj ^ (rowl & 7)) << 4));
    const float* gA = A  + (size_t)(by * 128 + rowl) * K + cj * 4;
    const float* gB = Bt + (size_t)(bx * 128 + rowl) * K + cj * 4;

    // prologue: fill 3 stages
    #pragma unroll
    for (int s = 0; s < 3; s++) {
        uint32_t sb = sbase + s * STAGE_BYTES;
        #pragma unroll
        for (int t = 0; t < 4; t++) {
            asm volatile("cp.async.cg.shared.global [%0], [%1], 16;"
                         :: "r"(sb + soA + t * 4096),
                            "l"(gA + (size_t)(32 * t) * K + s * 32) : "memory");
            asm volatile("cp.async.cg.shared.global [%0], [%1], 16;"
                         :: "r"(sb + 16384 + soA + t * 4096),
                            "l"(gB + (size_t)(32 * t) * K + s * 32) : "memory");
        }
        asm volatile("cp.async.commit_group;" ::: "memory");
    }

    float acc[2][8][4];
    #pragma unroll
    for (int mi = 0; mi < 2; mi++)
        #pragma unroll
        for (int ni = 0; ni < 8; ni++)
            #pragma unroll
            for (int r = 0; r < 4; r++) acc[mi][ni][r] = 0.0f;

    // ---- fragment addresses (bytes within stage) ----
    uint32_t aOffB[2][2], bOffB[8], coffB[4];
    #pragma unroll
    for (int mi = 0; mi < 2; mi++)
        #pragma unroll
        for (int p = 0; p < 2; p++)
            aOffB[mi][p] = (uint32_t)((wm * 32 + mi * 16 + g + p * 8) * 128);
    #pragma unroll
    for (int ni = 0; ni < 8; ni++)
        bOffB[ni] = (uint32_t)(16384 + (wnn * 64 + ni * 8 + g) * 128);
    #pragma unroll
    for (int s = 0; s < 4; s++)
        coffB[s] = (uint32_t)((((2 * s + (c >> 1)) ^ g) << 4) + (c & 1) * 8);

    for (int i = 0; i < nk; i++) {
        asm volatile("cp.async.wait_group 2;" ::: "memory");
        __syncthreads();
        const uint32_t sb = sbase + (i % 3) * STAGE_BYTES;

        #pragma unroll
        for (int s = 0; s < 4; s++) {
            const uint32_t off = coffB[s];
            uint2 av[2][2];
            #pragma unroll
            for (int mi = 0; mi < 2; mi++) {
                av[mi][0] = lds64(sb + aOffB[mi][0] + off);
                av[mi][1] = lds64(sb + aOffB[mi][1] + off);
            }
            uint2 bv[8];
            #pragma unroll
            for (int ni = 0; ni < 8; ni++)
                bv[ni] = lds64(sb + bOffB[ni] + off);
            #pragma unroll
            for (int mi = 0; mi < 2; mi++)
                #pragma unroll
                for (int ni = 0; ni < 8; ni++)
                    mma8(acc[mi][ni],
                         av[mi][0].x, av[mi][1].x, av[mi][0].y, av[mi][1].y,
                         bv[ni].x, bv[ni].y);
        }
        __syncthreads();

        const int j = i + 3;
        if (j < nk) {
            #pragma unroll
            for (int t = 0; t < 4; t++) {
                asm volatile("cp.async.cg.shared.global [%0], [%1], 16;"
                             :: "r"(sb + soA + t * 4096),
                                "l"(gA + (size_t)(32 * t) * K + j * 32) : "memory");
                asm volatile("cp.async.cg.shared.global [%0], [%1], 16;"
                             :: "r"(sb + 16384 + soA + t * 4096),
                                "l"(gB + (size_t)(32 * t) * K + j * 32) : "memory");
            }
        }
        asm volatile("cp.async.commit_group;" ::: "memory");
    }

    // ---- epilogue ----
    const int p0 = perm8(2 * c);       // physical col for logical 2c
    const int p1 = perm8(2 * c + 1);   // physical col for logical 2c+1
    #pragma unroll
    for (int mi = 0; mi < 2; mi++) {
        const int r0 = by * 128 + wm * 32 + mi * 16 + g;
        #pragma unroll
        for (int ni = 0; ni < 8; ni++) {
            const int colg = bx * 128 + wnn * 64 + ni * 8;
            const float bb0 = bias[colg + 2 * c];
            const float bb1 = bias[colg + 2 * c + 1];
            float v00 = acc[mi][ni][0] + bb0;
            float v01 = acc[mi][ni][1] + bb1;
            float v10 = acc[mi][ni][2] + bb0;
            float v11 = acc[mi][ni][3] + bb1;
            if (mode == 1) {
                v00 = rna_tf32(gelu_f(v00)); v01 = rna_tf32(gelu_f(v01));
                v10 = rna_tf32(gelu_f(v10)); v11 = rna_tf32(gelu_f(v11));
                float* c0 = C + (size_t)r0 * N + colg;
                float* c1 = C + (size_t)(r0 + 8) * N + colg;
                c0[p0] = v00; c0[p1] = v01;
                c1[p0] = v10; c1[p1] = v11;
            } else if (mode == 2) {
                const float* rr0 = res + (size_t)r0 * N + colg + 2 * c;
                const float* rr1 = res + (size_t)(r0 + 8) * N + colg + 2 * c;
                v00 += rr0[0]; v01 += rr0[1];
                v10 += rr1[0]; v11 += rr1[1];
                float2 o0; o0.x = v00; o0.y = v01;
                float2 o1; o1.x = v10; o1.y = v11;
                *(float2*)(C + (size_t)r0 * N + colg + 2 * c) = o0;
                *(float2*)(C + (size_t)(r0 + 8) * N + colg + 2 * c) = o1;
            } else {
                float2 o0; o0.x = v00; o0.y = v01;
                float2 o1; o1.x = v10; o1.y = v11;
                *(float2*)(C + (size_t)r0 * N + colg + 2 * c) = o0;
                *(float2*)(C + (size_t)(r0 + 8) * N + colg + 2 * c) = o1;
            }
        }
    }
    (void)wn;
}

// ---------------- flash attention + residual ---------------------------------
#define ATT_SMEM_FLOATS (64*64 + 64*65 + 64*64 + 8*8*64)

__global__ __launch_bounds__(256)
void attn_kernel(const float* __restrict__ x, float* __restrict__ x1,
                 float* __restrict__ x1r)
{
    extern __shared__ float sm[];
    float* Qs = sm;
    float* Ks = sm + 4096;
    float* Vs = sm + 4096 + 4160;
    float* Ps = sm + 4096 + 4160 + 4096;

    const int qt   = blockIdx.x;
    const int bh   = blockIdx.y;
    const int b    = bh >> 4;
    const int h    = bh & 15;
    const int tid  = threadIdx.x;
    const int lane = tid & 31;
    const int w    = tid >> 5;

    const size_t headoff = (size_t)b * T * H + (size_t)h * HD;
    const float* Qg = g_q + headoff;
    const float* Kg = g_k + headoff;
    const float* Vg = g_v + headoff;

    #pragma unroll
    for (int i = 0; i < 4; i++) {
        int e = tid + 256 * i;
        int r = e >> 4;
        int c = (e & 15) << 2;
        float4 v = *(const float4*)(Qg + (size_t)(qt * 64 + r) * H + c);
        Qs[r * 64 + c + 0] = v.x * 0.03125f;
        Qs[r * 64 + c + 1] = v.y * 0.03125f;
        Qs[r * 64 + c + 2] = v.z * 0.03125f;
        Qs[r * 64 + c + 3] = v.w * 0.03125f;
    }

    float m[8], l[8];
    float2 o[8];
    #pragma unroll
    for (int r = 0; r < 8; r++) { m[r] = -1e30f; l[r] = 0.0f; o[r] = make_float2(0.f, 0.f); }

    __syncthreads();

    for (int kt = 0; kt <= qt; kt++) {
        #pragma unroll
        for (int i = 0; i < 4; i++) {
            int e = tid + 256 * i;
            int r = e >> 4;
            int c = (e & 15) << 2;
            float4 kv = *(const float4*)(Kg + (size_t)(kt * 64 + r) * H + c);
            Ks[r * 65 + c + 0] = kv.x;
            Ks[r * 65 + c + 1] = kv.y;
            Ks[r * 65 + c + 2] = kv.z;
            Ks[r * 65 + c + 3] = kv.w;
            float4 vv = *(const float4*)(Vg + (size_t)(kt * 64 + r) * H + c);
            *(float4*)&Vs[r * 64 + c] = vv;
        }
        __syncthreads();

        float s0[8], s1[8];
        const float* k0p = &Ks[lane * 65];
        const float* k1p = &Ks[(lane + 32) * 65];
        #pragma unroll
        for (int rg = 0; rg < 2; rg++) {
            const float* qb = &Qs[(w * 8 + rg * 4) * 64];
            float a0[4], a1[4];
            #pragma unroll
            for (int rr = 0; rr < 4; rr++) { a0[rr] = 0.f; a1[rr] = 0.f; }
            #pragma unroll 16
            for (int d = 0; d < 64; d++) {
                float k0 = k0p[d];
                float k1 = k1p[d];
                #pragma unroll
                for (int rr = 0; rr < 4; rr++) {
                    float qv = qb[rr * 64 + d];
                    a0[rr] += qv * k0;
                    a1[rr] += qv * k1;
                }
            }
            #pragma unroll
            for (int rr = 0; rr < 4; rr++) { s0[rg * 4 + rr] = a0[rr]; s1[rg * 4 + rr] = a1[rr]; }
        }

        const bool diag = (kt == qt);
        #pragma unroll
        for (int r = 0; r < 8; r++) {
            const int rowi = w * 8 + r;
            float v0 = s0[r], v1 = s1[r];
            const bool m0 = (!diag) || (lane <= rowi);
            const bool m1 = (!diag) || (lane + 32 <= rowi);
            if (!m0) v0 = -1e30f;
            if (!m1) v1 = -1e30f;
            float mx = fmaxf(v0, v1);
            #pragma unroll
            for (int off = 16; off; off >>= 1)
                mx = fmaxf(mx, __shfl_xor_sync(0xffffffffu, mx, off));
            const float mn = fmaxf(m[r], mx);
            const float alpha = __expf(m[r] - mn);
            const float p0 = m0 ? __expf(v0 - mn) : 0.0f;
            const float p1 = m1 ? __expf(v1 - mn) : 0.0f;
            float ps = p0 + p1;
            #pragma unroll
            for (int off = 16; off; off >>= 1)
                ps += __shfl_xor_sync(0xffffffffu, ps, off);
            l[r] = l[r] * alpha + ps;
            m[r] = mn;
            o[r].x *= alpha;
            o[r].y *= alpha;
            Ps[w * 512 + r * 64 + lane]      = p0;
            Ps[w * 512 + r * 64 + lane + 32] = p1;
        }
        __syncwarp();

        const float* pw = &Ps[w * 512];
        #pragma unroll 8
        for (int j = 0; j < 64; j++) {
            float2 v = *(const float2*)&Vs[j * 64 + lane * 2];
            #pragma unroll
            for (int r = 0; r < 8; r++) {
                float p = pw[r * 64 + j];
                o[r].x += p * v.x;
                o[r].y += p * v.y;
            }
        }
        __syncthreads();
    }

    // epilogue: x1 exact; x1r rounded + k-permuted (for MLP1's A operand)
    const int cc = lane & 3;
    const int pp0 = perm8(2 * cc);
    const int pp1 = perm8(2 * cc + 1);
    #pragma unroll
    for (int r = 0; r < 8; r++) {
        const int trow = qt * 64 + w * 8 + r;
        const size_t base = (size_t)b * T * H + (size_t)trow * H + (size_t)h * HD + lane * 2;
        const size_t gb = base & ~(size_t)7;
        const float inv = 1.0f / l[r];
        float o0 = x[base + 0] + o[r].x * inv;
        float o1 = x[base + 1] + o[r].y * inv;
        x1[base + 0] = o0;
        x1[base + 1] = o1;
        x1r[gb + pp0] = rna_tf32(o0);
        x1r[gb + pp1] = rna_tf32(o1);
    }
}

// ---------------- launch -----------------------------------------------------
extern "C" void kernel_launch(void* const* d_in, const int* in_sizes, int n_in,
                              void* d_out, int out_size)
{
    const float* x  = (const float*)d_in[0];
    const float* Wq = (const float*)d_in[1];
    const float* bq = (const float*)d_in[2];
    const float* Wk = (const float*)d_in[3];
    const float* bk = (const float*)d_in[4];
    const float* Wv = (const float*)d_in[5];
    const float* bv = (const float*)d_in[6];
    const float* W1 = (const float*)d_in[7];
    const float* b1 = (const float*)d_in[8];
    const float* W2 = (const float*)d_in[9];
    const float* b2 = (const float*)d_in[10];
    float* out = (float*)d_out;

    float *q, *k, *v, *x1, *x1r, *xr, *h, *wqt, *wkt, *wvt, *w1t, *w2t;
    cudaGetSymbolAddress((void**)&q,    g_q);
    cudaGetSymbolAddress((void**)&k,    g_k);
    cudaGetSymbolAddress((void**)&v,    g_v);
    cudaGetSymbolAddress((void**)&x1,   g_x1);
    cudaGetSymbolAddress((void**)&x1r,  g_x1r);
    cudaGetSymbolAddress((void**)&xr,   g_xr);
    cudaGetSymbolAddress((void**)&h,    g_h);
    cudaGetSymbolAddress((void**)&wqt,  g_wqt);
    cudaGetSymbolAddress((void**)&wkt,  g_wkt);
    cudaGetSymbolAddress((void**)&wvt,  g_wvt);
    cudaGetSymbolAddress((void**)&w1t,  g_w1t);
    cudaGetSymbolAddress((void**)&w2t,  g_w2t);

    // prep: round+permute x, transpose+round+permute weights
    round_perm_k<<<(BT * H) / (256 * 8), 256>>>(x, xr, BT * H);
    dim3 tb(32, 8);
    transpose_rna_perm_k<<<dim3(H / 32,  H / 32),  tb>>>(Wq, wqt, H, H);
    transpose_rna_perm_k<<<dim3(H / 32,  H / 32),  tb>>>(Wk, wkt, H, H);
    transpose_rna_perm_k<<<dim3(H / 32,  H / 32),  tb>>>(Wv, wvt, H, H);
    transpose_rna_perm_k<<<dim3(FF / 32, H / 32),  tb>>>(W1, w1t, H, FF);
    transpose_rna_perm_k<<<dim3(H / 32,  FF / 32), tb>>>(W2, w2t, FF, H);

    cudaFuncSetAttribute(gemm_tf32, cudaFuncAttributeMaxDynamicSharedMemorySize, GEMM_SMEM);

    // QKV fused over grid.z
    gemm_tf32<<<dim3(H / 128, BT / 128, 3), 256, GEMM_SMEM>>>(
        xr, wqt, wkt, wvt, bq, bk, bv, q, k, v, nullptr, H, H, 0);

    const int att_smem = ATT_SMEM_FLOATS * (int)sizeof(float);
    cudaFuncSetAttribute(attn_kernel, cudaFuncAttributeMaxDynamicSharedMemorySize, att_smem);
    attn_kernel<<<dim3(T / 64, BATCH * NHEAD), 256, att_smem>>>(x, x1, x1r);

    // MLP1: h = rna(gelu(x1r @ W1t^T + b1)), k-permuted columns
    gemm_tf32<<<dim3(FF / 128, BT / 128, 1), 256, GEMM_SMEM>>>(
        x1r, w1t, w1t, w1t, b1, b1, b1, h, h, h, nullptr, H, FF, 1);

    // MLP2: out = h @ W2t^T + b2 + x1
    gemm_tf32<<<dim3(H / 128, BT / 128, 1), 256, GEMM_SMEM>>>(
        h, w2t, w2t, w2t, b2, b2, b2, out, out, out, x1, FF, H, 2);
}